// round 6
// baseline (speedup 1.0000x reference)
#include <cuda_runtime.h>
#include <cuda_bf16.h>
#include <math.h>
#include <stdint.h>

// ---------------------------------------------------------------------------
// Problem constants
// ---------------------------------------------------------------------------
#define D     1024
#define H     1024
#define E     8
#define B_MAX 16384

#define TMm 128          // CTA token tile
#define TNn 64           // CTA H tile
#define KC  32           // K chunk (bf16 elems)
#define NCH (D / KC)     // 32 chunks
#define NSTAGE 4

// SMEM stage layout (bytes). Rows of 32 bf16 padded to 40 (80 B) for
// conflict-free ldmatrix.
#define ROWB   80
#define S_AHI  0
#define S_ALO  10240                 // 128 rows * 80
#define S_WVH  20480
#define S_WVL  25600                 // 64 rows * 80
#define S_WGH  30720
#define S_WGL  35840
#define STAGE  40960
#define OFF_TOK (NSTAGE * STAGE)
#define OFF_WT  (NSTAGE * STAGE + 512)
#define SMEM_TOTAL (NSTAGE * STAGE + 1024)   // 164864

// ---------------------------------------------------------------------------
// Device scratch
// ---------------------------------------------------------------------------
__device__ int   g_cnt[E];
__device__ int   g_tok[E * B_MAX];
__device__ float g_wt [E * B_MAX];

__device__ __nv_bfloat16 g_xhi[B_MAX * D];
__device__ __nv_bfloat16 g_xlo[B_MAX * D];
__device__ __nv_bfloat16 g_wvhi[E * H * D];   // transposed: [E,H,D]
__device__ __nv_bfloat16 g_wvlo[E * H * D];
__device__ __nv_bfloat16 g_wghi[E * H * D];
__device__ __nv_bfloat16 g_wglo[E * H * D];

// ---------------------------------------------------------------------------
// PTX helpers (sm_80+ baseline features only)
// ---------------------------------------------------------------------------
__device__ __forceinline__ uint32_t smem_u32(const void* p) {
    uint32_t a;
    asm("{ .reg .u64 t; cvta.to.shared.u64 t, %1; cvt.u32.u64 %0, t; }"
        : "=r"(a) : "l"(p));
    return a;
}

__device__ __forceinline__ void cp16(uint32_t dst, const void* src) {
    asm volatile("cp.async.cg.shared.global [%0], [%1], 16;"
                 :: "r"(dst), "l"((unsigned long long)__cvta_generic_to_global(src)));
}
#define CP_COMMIT() asm volatile("cp.async.commit_group;" ::: "memory")
#define CP_WAIT2()  asm volatile("cp.async.wait_group 2;" ::: "memory")
#define CP_WAIT1()  asm volatile("cp.async.wait_group 1;" ::: "memory")
#define CP_WAIT0()  asm volatile("cp.async.wait_group 0;" ::: "memory")

__device__ __forceinline__ void ldmx4(uint32_t* r, uint32_t addr) {
    asm volatile("ldmatrix.sync.aligned.m8n8.x4.shared.b16 {%0,%1,%2,%3}, [%4];"
                 : "=r"(r[0]), "=r"(r[1]), "=r"(r[2]), "=r"(r[3]) : "r"(addr));
}

__device__ __forceinline__ void mma16816(float* c, const uint32_t* a,
                                         const uint32_t* b) {
    asm volatile(
        "mma.sync.aligned.m16n8k16.row.col.f32.bf16.bf16.f32 "
        "{%0,%1,%2,%3}, {%4,%5,%6,%7}, {%8,%9}, {%0,%1,%2,%3};"
        : "+f"(c[0]), "+f"(c[1]), "+f"(c[2]), "+f"(c[3])
        : "r"(a[0]), "r"(a[1]), "r"(a[2]), "r"(a[3]), "r"(b[0]), "r"(b[1]));
}

// ---------------------------------------------------------------------------
// Fused: zero output + reset counters + x -> bf16 hi/lo split
// ---------------------------------------------------------------------------
__global__ void prep_kernel(const float* __restrict__ x, float* __restrict__ out,
                            int nx4, int no4) {
    if (blockIdx.x == 0 && threadIdx.x < E) g_cnt[threadIdx.x] = 0;
    int stride = gridDim.x * blockDim.x;
    int t0 = blockIdx.x * blockDim.x + threadIdx.x;
    float4 z = make_float4(0.f, 0.f, 0.f, 0.f);
    for (int i = t0; i < no4; i += stride) ((float4*)out)[i] = z;
    for (int i = t0; i < nx4; i += stride) {
        float4 v = ((const float4*)x)[i];
        __nv_bfloat16 h0 = __float2bfloat16(v.x);
        __nv_bfloat16 h1 = __float2bfloat16(v.y);
        __nv_bfloat16 h2 = __float2bfloat16(v.z);
        __nv_bfloat16 h3 = __float2bfloat16(v.w);
        __nv_bfloat16 l0 = __float2bfloat16(v.x - __bfloat162float(h0));
        __nv_bfloat16 l1 = __float2bfloat16(v.y - __bfloat162float(h1));
        __nv_bfloat16 l2 = __float2bfloat16(v.z - __bfloat162float(h2));
        __nv_bfloat16 l3 = __float2bfloat16(v.w - __bfloat162float(h3));
        ((__nv_bfloat162*)g_xhi)[2 * i + 0] = __nv_bfloat162(h0, h1);
        ((__nv_bfloat162*)g_xhi)[2 * i + 1] = __nv_bfloat162(h2, h3);
        ((__nv_bfloat162*)g_xlo)[2 * i + 0] = __nv_bfloat162(l0, l1);
        ((__nv_bfloat162*)g_xlo)[2 * i + 1] = __nv_bfloat162(l2, l3);
    }
}

// ---------------------------------------------------------------------------
// Router (validated)
// ---------------------------------------------------------------------------
__global__ void router_kernel(const float* __restrict__ x,
                              const float* __restrict__ gate_w,
                              const float* __restrict__ gate_b,
                              int B) {
    int warp = (blockIdx.x * blockDim.x + threadIdx.x) >> 5;
    int lane = threadIdx.x & 31;
    if (warp >= B) return;

    const float4* x4 = (const float4*)x + (long)warp * (D / 4);
    const float4* w4 = (const float4*)gate_w;

    float acc[E];
#pragma unroll
    for (int e = 0; e < E; e++) acc[e] = 0.f;
#pragma unroll
    for (int i = 0; i < D / 4 / 32; i++) {
        float4 xv = x4[lane + i * 32];
#pragma unroll
        for (int e = 0; e < E; e++) {
            float4 wv = w4[e * (D / 4) + lane + i * 32];
            acc[e] += xv.x * wv.x + xv.y * wv.y + xv.z * wv.z + xv.w * wv.w;
        }
    }
#pragma unroll
    for (int e = 0; e < E; e++) {
#pragma unroll
        for (int o = 16; o > 0; o >>= 1)
            acc[e] += __shfl_xor_sync(0xffffffffu, acc[e], o);
    }

    if (lane == 0) {
        float l[E];
        float mx = -1e30f;
#pragma unroll
        for (int e = 0; e < E; e++) {
            l[e] = acc[e] + gate_b[e];
            mx = fmaxf(mx, l[e]);
        }
        int i1 = 0;
#pragma unroll
        for (int e = 1; e < E; e++) if (l[e] > l[i1]) i1 = e;
        int i2 = (i1 == 0) ? 1 : 0;
#pragma unroll
        for (int e = 0; e < E; e++) if (e != i1 && l[e] > l[i2]) i2 = e;

        float s = 0.f;
#pragma unroll
        for (int e = 0; e < E; e++) s += expf(l[e] - mx);
        float p1 = expf(l[i1] - mx) / s;
        float p2 = expf(l[i2] - mx) / s;

        int pos1 = atomicAdd(&g_cnt[i1], 1);
        g_tok[i1 * B_MAX + pos1] = warp;
        g_wt [i1 * B_MAX + pos1] = p1;
        int pos2 = atomicAdd(&g_cnt[i2], 1);
        g_tok[i2 * B_MAX + pos2] = warp;
        g_wt [i2 * B_MAX + pos2] = p2;
    }
}

// ---------------------------------------------------------------------------
// Wv/Wg [E,D,H] fp32 -> [E,H,D] bf16 hi/lo (transposed, K-major)
// ---------------------------------------------------------------------------
__global__ void convert_w_kernel(const float* __restrict__ Wv,
                                 const float* __restrict__ Wg) {
    __shared__ float tile[32][33];
    int which = blockIdx.z & 1;
    int e = blockIdx.z >> 1;
    const float* src = which ? Wg : Wv;
    __nv_bfloat16* dhi = which ? g_wghi : g_wvhi;
    __nv_bfloat16* dlo = which ? g_wglo : g_wvlo;

    int h0 = blockIdx.x * 32, d0 = blockIdx.y * 32;
    int tx = threadIdx.x, ty = threadIdx.y;

#pragma unroll
    for (int j = 0; j < 4; j++) {
        int dl = ty + j * 8;
        tile[dl][tx] = src[((size_t)e * D + d0 + dl) * H + h0 + tx];
    }
    __syncthreads();
#pragma unroll
    for (int j = 0; j < 4; j++) {
        int hl = ty + j * 8;
        float a = tile[tx][hl];
        __nv_bfloat16 hi = __float2bfloat16(a);
        __nv_bfloat16 lo = __float2bfloat16(a - __bfloat162float(hi));
        size_t o = ((size_t)e * H + h0 + hl) * D + d0 + tx;
        dhi[o] = hi;
        dlo[o] = lo;
    }
}

// ---------------------------------------------------------------------------
// Stage loader: 8 x cp.async(16B) per thread
// ---------------------------------------------------------------------------
__device__ __forceinline__ void load_stage(uint32_t st, int k0, int e, int n0,
                                           int tid,
                                           const int* __restrict__ s_tok) {
#pragma unroll
    for (int i = 0; i < 2; i++) {
        int idx = tid + i * 256;           // 0..511
        int row = idx >> 2, seg = idx & 3;
        size_t go = (size_t)s_tok[row] * D + k0 + seg * 8;
        uint32_t dst = st + (uint32_t)(row * ROWB + seg * 16);
        cp16(dst + S_AHI, g_xhi + go);
        cp16(dst + S_ALO, g_xlo + go);
    }
#pragma unroll
    for (int i = 0; i < 2; i++) {
        int idx = tid + i * 256;           // 0..511
        int mat = idx >> 8;                // 0=v, 1=g
        int row = (idx >> 2) & 63, seg = idx & 3;
        size_t go = ((size_t)e * H + n0 + row) * D + k0 + seg * 8;
        uint32_t dst = st + (uint32_t)(row * ROWB + seg * 16) +
                       (mat ? S_WGH : S_WVH);
        cp16(dst, (mat ? g_wghi : g_wvhi) + go);
        cp16(dst + (uint32_t)(S_WVL - S_WVH), (mat ? g_wglo : g_wvlo) + go);
    }
}

// ---------------------------------------------------------------------------
// Grouped gather-GEMM: mma.sync bf16 3-pass fp32 emulation.
// 4-stage cp.async pipeline, ONE __syncthreads per chunk.
// grid (B/128, H/64, E), 256 threads (4 M-warps x 2 N-warps)
// ---------------------------------------------------------------------------
__global__ __launch_bounds__(256, 1)
void moe_hmma_kernel(float* __restrict__ out) {
    const int e = blockIdx.z;
    const int cnt = g_cnt[e];
    const int m_base = blockIdx.x * TMm;
    if (m_base >= cnt) return;
    const int n0 = blockIdx.y * TNn;

    extern __shared__ char sm[];
    const uint32_t sb = smem_u32(sm);
    const int tid = threadIdx.x;
    const int lane = tid & 31;
    const int wid = tid >> 5;
    const int wm = wid & 3;          // rows wm*32
    const int wn = wid >> 2;         // cols wn*32

    int*   s_tok = (int*)(sm + OFF_TOK);
    float* s_wt  = (float*)(sm + OFF_WT);
    if (tid < TMm) {
        int mg = m_base + tid;
        s_tok[tid] = (mg < cnt) ? g_tok[e * B_MAX + mg] : 0;
        s_wt [tid] = (mg < cnt) ? g_wt [e * B_MAX + mg] : 0.f;
    }
    __syncthreads();

    float cv[2][4][4], cg[2][4][4];
#pragma unroll
    for (int mt = 0; mt < 2; mt++)
#pragma unroll
        for (int nt = 0; nt < 4; nt++)
#pragma unroll
            for (int q = 0; q < 4; q++) { cv[mt][nt][q] = 0.f; cg[mt][nt][q] = 0.f; }

    // Prologue: stage chunks 0..2
    load_stage(sb + 0 * STAGE, 0 * KC, e, n0, tid, s_tok); CP_COMMIT();
    load_stage(sb + 1 * STAGE, 1 * KC, e, n0, tid, s_tok); CP_COMMIT();
    load_stage(sb + 2 * STAGE, 2 * KC, e, n0, tid, s_tok); CP_COMMIT();

    // ldmatrix lane addressing (constant per thread)
    const int a_row = (lane & 15);
    const int a_col = (lane >> 4) * 8;
    const int b_row = (lane & 7) + ((lane >> 4) << 3);
    const int b_col = ((lane >> 3) & 1) * 8;

    for (int c = 0; c < NCH; c++) {
        if (c <= NCH - 3)      CP_WAIT2();
        else if (c == NCH - 2) CP_WAIT1();
        else                   CP_WAIT0();
        __syncthreads();

        // Issue next-stage loads first so LDGSTS overlaps the MMAs below.
        if (c + 3 < NCH) {
            load_stage(sb + (uint32_t)((c + 3) & 3) * STAGE, (c + 3) * KC,
                       e, n0, tid, s_tok);
            CP_COMMIT();
        }

        uint32_t st = sb + (uint32_t)(c & 3) * STAGE;

#pragma unroll
        for (int ks = 0; ks < 2; ks++) {
            uint32_t ah[2][4], al[2][4];
#pragma unroll
            for (int mt = 0; mt < 2; mt++) {
                uint32_t ad = st + S_AHI +
                    (uint32_t)((wm * 32 + mt * 16 + a_row) * ROWB +
                               (ks * 16 + a_col) * 2);
                ldmx4(ah[mt], ad);
                ldmx4(al[mt], ad + (S_ALO - S_AHI));
            }
            uint32_t bvh[2][4], bvl[2][4], bgh[2][4], bgl[2][4];
#pragma unroll
            for (int p = 0; p < 2; p++) {
                uint32_t bd = st + S_WVH +
                    (uint32_t)((wn * 32 + p * 16 + b_row) * ROWB +
                               (ks * 16 + b_col) * 2);
                ldmx4(bvh[p], bd);
                ldmx4(bvl[p], bd + (S_WVL - S_WVH));
                ldmx4(bgh[p], bd + (S_WGH - S_WVH));
                ldmx4(bgl[p], bd + (S_WGL - S_WVH));
            }
#pragma unroll
            for (int mt = 0; mt < 2; mt++) {
#pragma unroll
                for (int nt = 0; nt < 4; nt++) {
                    int p = nt >> 1, q = (nt & 1) * 2;
                    mma16816(cv[mt][nt], ah[mt], &bvh[p][q]);
                    mma16816(cv[mt][nt], ah[mt], &bvl[p][q]);
                    mma16816(cv[mt][nt], al[mt], &bvh[p][q]);
                    mma16816(cg[mt][nt], ah[mt], &bgh[p][q]);
                    mma16816(cg[mt][nt], ah[mt], &bgl[p][q]);
                    mma16816(cg[mt][nt], al[mt], &bgh[p][q]);
                }
            }
        }
    }

    // Epilogue: fused SwiGLU + weighted atomic combine
    const int er0 = wm * 32 + (lane >> 2);
    const int ec0 = wn * 32 + (lane & 3) * 2;
#pragma unroll
    for (int mt = 0; mt < 2; mt++) {
#pragma unroll
        for (int half = 0; half < 2; half++) {
            int r = er0 + mt * 16 + half * 8;
            int mg = m_base + r;
            if (mg < cnt) {
                int tok = s_tok[r];
                float w = s_wt[r];
                float* op = out + (size_t)tok * H + n0;
#pragma unroll
                for (int nt = 0; nt < 4; nt++) {
#pragma unroll
                    for (int j = 0; j < 2; j++) {
                        float v = cv[mt][nt][half * 2 + j];
                        float g = cg[mt][nt][half * 2 + j];
                        float sg = 1.f / (1.f + __expf(-g));
                        atomicAdd(op + ec0 + nt * 8 + j, w * v * sg);
                    }
                }
            }
        }
    }
}

// ---------------------------------------------------------------------------
extern "C" void kernel_launch(void* const* d_in, const int* in_sizes, int n_in,
                              void* d_out, int out_size) {
    const float* x  = (const float*)d_in[0];
    const float* Wv = (const float*)d_in[1];
    const float* Wg = (const float*)d_in[2];
    const float* gw = (const float*)d_in[3];
    const float* gb = (const float*)d_in[4];
    float* out = (float*)d_out;
    (void)n_in;

    int B = in_sizes[0] / D;

    cudaFuncSetAttribute(moe_hmma_kernel,
                         cudaFuncAttributeMaxDynamicSharedMemorySize, SMEM_TOTAL);

    prep_kernel<<<1024, 256>>>(x, out, B * D / 4, out_size / 4);
    router_kernel<<<(B * 32 + 255) / 256, 256>>>(x, gw, gb, B);
    convert_w_kernel<<<dim3(H / 32, D / 32, 2 * E), dim3(32, 8)>>>(Wv, Wg);

    dim3 grid((B + TMm - 1) / TMm, H / TNn, E);
    moe_hmma_kernel<<<grid, 256, SMEM_TOTAL>>>(out);
}

// round 7
// speedup vs baseline: 1.0056x; 1.0056x over previous
#include <cuda_runtime.h>
#include <cuda_bf16.h>
#include <math.h>
#include <stdint.h>

// ---------------------------------------------------------------------------
// Problem constants
// ---------------------------------------------------------------------------
#define D     1024
#define H     1024
#define E     8
#define B_MAX 16384

#define TMm 128          // CTA token tile
#define TNn 64           // CTA H tile
#define KC  32           // K chunk (bf16 elems)
#define NCH (D / KC)     // 32 chunks
#define NSTAGE 4

// SMEM stage layout (bytes). Rows of 32 bf16 padded to 40 (80 B) for
// conflict-free ldmatrix.
#define ROWB   80
#define S_AHI  0
#define S_ALO  10240                 // 128 rows * 80
#define S_WVH  20480
#define S_WVL  25600                 // 64 rows * 80
#define S_WGH  30720
#define S_WGL  35840
#define STAGE  40960
#define OFF_TOK (NSTAGE * STAGE)
#define OFF_WT  (NSTAGE * STAGE + 512)
#define SMEM_TOTAL (NSTAGE * STAGE + 1024)   // 164864

// ---------------------------------------------------------------------------
// Device scratch
// ---------------------------------------------------------------------------
__device__ int   g_cnt[E];
__device__ int   g_tok[E * B_MAX];
__device__ float g_wt [E * B_MAX];

__device__ __nv_bfloat16 g_xhi[B_MAX * D];
__device__ __nv_bfloat16 g_xlo[B_MAX * D];
__device__ __nv_bfloat16 g_wvhi[E * H * D];   // transposed: [E,H,D]
__device__ __nv_bfloat16 g_wvlo[E * H * D];
__device__ __nv_bfloat16 g_wghi[E * H * D];
__device__ __nv_bfloat16 g_wglo[E * H * D];

// ---------------------------------------------------------------------------
// PTX helpers (sm_80+ baseline features only)
// ---------------------------------------------------------------------------
__device__ __forceinline__ uint32_t smem_u32(const void* p) {
    uint32_t a;
    asm("{ .reg .u64 t; cvta.to.shared.u64 t, %1; cvt.u32.u64 %0, t; }"
        : "=r"(a) : "l"(p));
    return a;
}

__device__ __forceinline__ void cp16(uint32_t dst, const void* src) {
    asm volatile("cp.async.cg.shared.global [%0], [%1], 16;"
                 :: "r"(dst), "l"((unsigned long long)__cvta_generic_to_global(src)));
}
#define CP_COMMIT() asm volatile("cp.async.commit_group;" ::: "memory")
#define CP_WAIT2()  asm volatile("cp.async.wait_group 2;" ::: "memory")
#define CP_WAIT1()  asm volatile("cp.async.wait_group 1;" ::: "memory")
#define CP_WAIT0()  asm volatile("cp.async.wait_group 0;" ::: "memory")

__device__ __forceinline__ void ldmx4(uint32_t* r, uint32_t addr) {
    asm volatile("ldmatrix.sync.aligned.m8n8.x4.shared.b16 {%0,%1,%2,%3}, [%4];"
                 : "=r"(r[0]), "=r"(r[1]), "=r"(r[2]), "=r"(r[3]) : "r"(addr));
}

__device__ __forceinline__ void mma16816(float* c, const uint32_t* a,
                                         const uint32_t* b) {
    asm volatile(
        "mma.sync.aligned.m16n8k16.row.col.f32.bf16.bf16.f32 "
        "{%0,%1,%2,%3}, {%4,%5,%6,%7}, {%8,%9}, {%0,%1,%2,%3};"
        : "+f"(c[0]), "+f"(c[1]), "+f"(c[2]), "+f"(c[3])
        : "r"(a[0]), "r"(a[1]), "r"(a[2]), "r"(a[3]), "r"(b[0]), "r"(b[1]));
}

// ---------------------------------------------------------------------------
// Fused: zero output + reset counters + x -> bf16 hi/lo split
// ---------------------------------------------------------------------------
__global__ void prep_kernel(const float* __restrict__ x, float* __restrict__ out,
                            int nx4, int no4) {
    if (blockIdx.x == 0 && threadIdx.x < E) g_cnt[threadIdx.x] = 0;
    int stride = gridDim.x * blockDim.x;
    int t0 = blockIdx.x * blockDim.x + threadIdx.x;
    float4 z = make_float4(0.f, 0.f, 0.f, 0.f);
    for (int i = t0; i < no4; i += stride) ((float4*)out)[i] = z;
    for (int i = t0; i < nx4; i += stride) {
        float4 v = ((const float4*)x)[i];
        __nv_bfloat16 h0 = __float2bfloat16(v.x);
        __nv_bfloat16 h1 = __float2bfloat16(v.y);
        __nv_bfloat16 h2 = __float2bfloat16(v.z);
        __nv_bfloat16 h3 = __float2bfloat16(v.w);
        __nv_bfloat16 l0 = __float2bfloat16(v.x - __bfloat162float(h0));
        __nv_bfloat16 l1 = __float2bfloat16(v.y - __bfloat162float(h1));
        __nv_bfloat16 l2 = __float2bfloat16(v.z - __bfloat162float(h2));
        __nv_bfloat16 l3 = __float2bfloat16(v.w - __bfloat162float(h3));
        ((__nv_bfloat162*)g_xhi)[2 * i + 0] = __nv_bfloat162(h0, h1);
        ((__nv_bfloat162*)g_xhi)[2 * i + 1] = __nv_bfloat162(h2, h3);
        ((__nv_bfloat162*)g_xlo)[2 * i + 0] = __nv_bfloat162(l0, l1);
        ((__nv_bfloat162*)g_xlo)[2 * i + 1] = __nv_bfloat162(l2, l3);
    }
}

// ---------------------------------------------------------------------------
// Router (validated)
// ---------------------------------------------------------------------------
__global__ void router_kernel(const float* __restrict__ x,
                              const float* __restrict__ gate_w,
                              const float* __restrict__ gate_b,
                              int B) {
    int warp = (blockIdx.x * blockDim.x + threadIdx.x) >> 5;
    int lane = threadIdx.x & 31;
    if (warp >= B) return;

    const float4* x4 = (const float4*)x + (long)warp * (D / 4);
    const float4* w4 = (const float4*)gate_w;

    float acc[E];
#pragma unroll
    for (int e = 0; e < E; e++) acc[e] = 0.f;
#pragma unroll
    for (int i = 0; i < D / 4 / 32; i++) {
        float4 xv = x4[lane + i * 32];
#pragma unroll
        for (int e = 0; e < E; e++) {
            float4 wv = w4[e * (D / 4) + lane + i * 32];
            acc[e] += xv.x * wv.x + xv.y * wv.y + xv.z * wv.z + xv.w * wv.w;
        }
    }
#pragma unroll
    for (int e = 0; e < E; e++) {
#pragma unroll
        for (int o = 16; o > 0; o >>= 1)
            acc[e] += __shfl_xor_sync(0xffffffffu, acc[e], o);
    }

    if (lane == 0) {
        float l[E];
        float mx = -1e30f;
#pragma unroll
        for (int e = 0; e < E; e++) {
            l[e] = acc[e] + gate_b[e];
            mx = fmaxf(mx, l[e]);
        }
        int i1 = 0;
#pragma unroll
        for (int e = 1; e < E; e++) if (l[e] > l[i1]) i1 = e;
        int i2 = (i1 == 0) ? 1 : 0;
#pragma unroll
        for (int e = 0; e < E; e++) if (e != i1 && l[e] > l[i2]) i2 = e;

        float s = 0.f;
#pragma unroll
        for (int e = 0; e < E; e++) s += expf(l[e] - mx);
        float p1 = expf(l[i1] - mx) / s;
        float p2 = expf(l[i2] - mx) / s;

        int pos1 = atomicAdd(&g_cnt[i1], 1);
        g_tok[i1 * B_MAX + pos1] = warp;
        g_wt [i1 * B_MAX + pos1] = p1;
        int pos2 = atomicAdd(&g_cnt[i2], 1);
        g_tok[i2 * B_MAX + pos2] = warp;
        g_wt [i2 * B_MAX + pos2] = p2;
    }
}

// ---------------------------------------------------------------------------
// Wv/Wg [E,D,H] fp32 -> [E,H,D] bf16 hi/lo (transposed, K-major)
// ---------------------------------------------------------------------------
__global__ void convert_w_kernel(const float* __restrict__ Wv,
                                 const float* __restrict__ Wg) {
    __shared__ float tile[32][33];
    int which = blockIdx.z & 1;
    int e = blockIdx.z >> 1;
    const float* src = which ? Wg : Wv;
    __nv_bfloat16* dhi = which ? g_wghi : g_wvhi;
    __nv_bfloat16* dlo = which ? g_wglo : g_wvlo;

    int h0 = blockIdx.x * 32, d0 = blockIdx.y * 32;
    int tx = threadIdx.x, ty = threadIdx.y;

#pragma unroll
    for (int j = 0; j < 4; j++) {
        int dl = ty + j * 8;
        tile[dl][tx] = src[((size_t)e * D + d0 + dl) * H + h0 + tx];
    }
    __syncthreads();
#pragma unroll
    for (int j = 0; j < 4; j++) {
        int hl = ty + j * 8;
        float a = tile[tx][hl];
        __nv_bfloat16 hi = __float2bfloat16(a);
        __nv_bfloat16 lo = __float2bfloat16(a - __bfloat162float(hi));
        size_t o = ((size_t)e * H + h0 + hl) * D + d0 + tx;
        dhi[o] = hi;
        dlo[o] = lo;
    }
}

// ---------------------------------------------------------------------------
// Stage loader: 8 x cp.async(16B) per thread
// ---------------------------------------------------------------------------
__device__ __forceinline__ void load_stage(uint32_t st, int k0, int e, int n0,
                                           int tid,
                                           const int* __restrict__ s_tok) {
#pragma unroll
    for (int i = 0; i < 2; i++) {
        int idx = tid + i * 256;           // 0..511
        int row = idx >> 2, seg = idx & 3;
        size_t go = (size_t)s_tok[row] * D + k0 + seg * 8;
        uint32_t dst = st + (uint32_t)(row * ROWB + seg * 16);
        cp16(dst + S_AHI, g_xhi + go);
        cp16(dst + S_ALO, g_xlo + go);
    }
#pragma unroll
    for (int i = 0; i < 2; i++) {
        int idx = tid + i * 256;           // 0..511
        int mat = idx >> 8;                // 0=v, 1=g
        int row = (idx >> 2) & 63, seg = idx & 3;
        size_t go = ((size_t)e * H + n0 + row) * D + k0 + seg * 8;
        uint32_t dst = st + (uint32_t)(row * ROWB + seg * 16) +
                       (mat ? S_WGH : S_WVH);
        cp16(dst, (mat ? g_wghi : g_wvhi) + go);
        cp16(dst + (uint32_t)(S_WVL - S_WVH), (mat ? g_wglo : g_wvlo) + go);
    }
}

// ---------------------------------------------------------------------------
// Grouped gather-GEMM: mma.sync bf16 3-pass fp32 emulation.
// 4-stage cp.async pipeline, ONE __syncthreads per chunk.
// grid (B/128, H/64, E), 256 threads (4 M-warps x 2 N-warps)
// ---------------------------------------------------------------------------
__global__ __launch_bounds__(256, 1)
void moe_hmma_kernel(float* __restrict__ out) {
    const int e = blockIdx.z;
    const int cnt = g_cnt[e];
    const int m_base = blockIdx.x * TMm;
    if (m_base >= cnt) return;
    const int n0 = blockIdx.y * TNn;

    extern __shared__ char sm[];
    const uint32_t sb = smem_u32(sm);
    const int tid = threadIdx.x;
    const int lane = tid & 31;
    const int wid = tid >> 5;
    const int wm = wid & 3;          // rows wm*32
    const int wn = wid >> 2;         // cols wn*32

    int*   s_tok = (int*)(sm + OFF_TOK);
    float* s_wt  = (float*)(sm + OFF_WT);
    if (tid < TMm) {
        int mg = m_base + tid;
        s_tok[tid] = (mg < cnt) ? g_tok[e * B_MAX + mg] : 0;
        s_wt [tid] = (mg < cnt) ? g_wt [e * B_MAX + mg] : 0.f;
    }
    __syncthreads();

    float cv[2][4][4], cg[2][4][4];
#pragma unroll
    for (int mt = 0; mt < 2; mt++)
#pragma unroll
        for (int nt = 0; nt < 4; nt++)
#pragma unroll
            for (int q = 0; q < 4; q++) { cv[mt][nt][q] = 0.f; cg[mt][nt][q] = 0.f; }

    // Prologue: stage chunks 0..2
    load_stage(sb + 0 * STAGE, 0 * KC, e, n0, tid, s_tok); CP_COMMIT();
    load_stage(sb + 1 * STAGE, 1 * KC, e, n0, tid, s_tok); CP_COMMIT();
    load_stage(sb + 2 * STAGE, 2 * KC, e, n0, tid, s_tok); CP_COMMIT();

    // ldmatrix lane addressing (constant per thread)
    const int a_row = (lane & 15);
    const int a_col = (lane >> 4) * 8;
    const int b_row = (lane & 7) + ((lane >> 4) << 3);
    const int b_col = ((lane >> 3) & 1) * 8;

    for (int c = 0; c < NCH; c++) {
        if (c <= NCH - 3)      CP_WAIT2();
        else if (c == NCH - 2) CP_WAIT1();
        else                   CP_WAIT0();
        __syncthreads();

        // Issue next-stage loads first so LDGSTS overlaps the MMAs below.
        if (c + 3 < NCH) {
            load_stage(sb + (uint32_t)((c + 3) & 3) * STAGE, (c + 3) * KC,
                       e, n0, tid, s_tok);
            CP_COMMIT();
        }

        uint32_t st = sb + (uint32_t)(c & 3) * STAGE;

#pragma unroll
        for (int ks = 0; ks < 2; ks++) {
            uint32_t ah[2][4], al[2][4];
#pragma unroll
            for (int mt = 0; mt < 2; mt++) {
                uint32_t ad = st + S_AHI +
                    (uint32_t)((wm * 32 + mt * 16 + a_row) * ROWB +
                               (ks * 16 + a_col) * 2);
                ldmx4(ah[mt], ad);
                ldmx4(al[mt], ad + (S_ALO - S_AHI));
            }
            uint32_t bvh[2][4], bvl[2][4], bgh[2][4], bgl[2][4];
#pragma unroll
            for (int p = 0; p < 2; p++) {
                uint32_t bd = st + S_WVH +
                    (uint32_t)((wn * 32 + p * 16 + b_row) * ROWB +
                               (ks * 16 + b_col) * 2);
                ldmx4(bvh[p], bd);
                ldmx4(bvl[p], bd + (S_WVL - S_WVH));
                ldmx4(bgh[p], bd + (S_WGH - S_WVH));
                ldmx4(bgl[p], bd + (S_WGL - S_WVH));
            }
#pragma unroll
            for (int mt = 0; mt < 2; mt++) {
#pragma unroll
                for (int nt = 0; nt < 4; nt++) {
                    int p = nt >> 1, q = (nt & 1) * 2;
                    mma16816(cv[mt][nt], ah[mt], &bvh[p][q]);
                    mma16816(cv[mt][nt], ah[mt], &bvl[p][q]);
                    mma16816(cv[mt][nt], al[mt], &bvh[p][q]);
                    mma16816(cg[mt][nt], ah[mt], &bgh[p][q]);
                    mma16816(cg[mt][nt], ah[mt], &bgl[p][q]);
                    mma16816(cg[mt][nt], al[mt], &bgh[p][q]);
                }
            }
        }
    }

    // Epilogue: fused SwiGLU + weighted atomic combine
    const int er0 = wm * 32 + (lane >> 2);
    const int ec0 = wn * 32 + (lane & 3) * 2;
#pragma unroll
    for (int mt = 0; mt < 2; mt++) {
#pragma unroll
        for (int half = 0; half < 2; half++) {
            int r = er0 + mt * 16 + half * 8;
            int mg = m_base + r;
            if (mg < cnt) {
                int tok = s_tok[r];
                float w = s_wt[r];
                float* op = out + (size_t)tok * H + n0;
#pragma unroll
                for (int nt = 0; nt < 4; nt++) {
#pragma unroll
                    for (int j = 0; j < 2; j++) {
                        float v = cv[mt][nt][half * 2 + j];
                        float g = cg[mt][nt][half * 2 + j];
                        float sg = 1.f / (1.f + __expf(-g));
                        atomicAdd(op + ec0 + nt * 8 + j, w * v * sg);
                    }
                }
            }
        }
    }
}

// ---------------------------------------------------------------------------
extern "C" void kernel_launch(void* const* d_in, const int* in_sizes, int n_in,
                              void* d_out, int out_size) {
    const float* x  = (const float*)d_in[0];
    const float* Wv = (const float*)d_in[1];
    const float* Wg = (const float*)d_in[2];
    const float* gw = (const float*)d_in[3];
    const float* gb = (const float*)d_in[4];
    float* out = (float*)d_out;
    (void)n_in;

    int B = in_sizes[0] / D;

    cudaFuncSetAttribute(moe_hmma_kernel,
                         cudaFuncAttributeMaxDynamicSharedMemorySize, SMEM_TOTAL);

    prep_kernel<<<1024, 256>>>(x, out, B * D / 4, out_size / 4);
    router_kernel<<<(B * 32 + 255) / 256, 256>>>(x, gw, gb, B);
    convert_w_kernel<<<dim3(H / 32, D / 32, 2 * E), dim3(32, 8)>>>(Wv, Wg);

    dim3 grid((B + TMm - 1) / TMm, H / TNn, E);
    moe_hmma_kernel<<<grid, 256, SMEM_TOTAL>>>(out);
}